// round 10
// baseline (speedup 1.0000x reference)
#include <cuda_runtime.h>
#include <cstdint>

#define DIM     512
#define D_INNER 1024
#define DT_RANK 32
#define D_STATE 16
#define B_SZ    4
#define N_TOK   4097
#define CLUSTER_N 8
#define CH_THREADS 512

// ---------------- scratch (device globals, allocation-free) ----------------
__device__ __align__(16) float g_q    [B_SZ * DIM];
__device__ __align__(16) float g_xs   [B_SZ * D_INNER];
__device__ __align__(16) float g_sz   [B_SZ * D_INNER];
__device__ __align__(16) float g_y    [B_SZ * D_INNER];
__device__ __align__(16) float g_mixed[B_SZ * DIM];

// ---------------- helpers ----------------
__device__ __forceinline__ float siluf(float x) { return x / (1.0f + __expf(-x)); }
__device__ __forceinline__ float softplusf(float x) {
    return (x > 20.0f) ? x : log1pf(__expf(x));
}
__device__ __forceinline__ void pf_l2(const float* p) {
    asm volatile("prefetch.global.L2 [%0];" :: "l"(p));
}
#define CSYNC() do { \
    asm volatile("barrier.cluster.arrive.aligned;" ::: "memory"); \
    asm volatile("barrier.cluster.wait.aligned;" ::: "memory"); \
} while (0)

// packed f32x2 FMA: acc += a * b (elementwise on two packed floats)
__device__ __forceinline__ void fma2(unsigned long long& acc,
                                     unsigned long long a, unsigned long long b) {
    asm("fma.rn.f32x2 %0, %1, %2, %0;" : "+l"(acc) : "l"(a), "l"(b));
}

// Preload NB batch activation slices (P4 float4 per lane each) into registers.
template <int P4, int NB>
__device__ __forceinline__ void load_act(ulonglong2 a[NB][P4],
                                         const float* s_act, int strideF) {
    int lane = threadIdx.x & 31;
#pragma unroll
    for (int b = 0; b < NB; b++) {
        const ulonglong2* p = (const ulonglong2*)(s_act + b * strideF);
#pragma unroll
        for (int i = 0; i < P4; i++) a[b][i] = p[lane + 32 * i];
    }
}

// One weight row vs NB register-resident activations -> NB warp-reduced dots.
template <int P4, int NB>
__device__ __forceinline__ void rows_dot(const ulonglong2 a[NB][P4],
                                         const float* wrow, float out[NB]) {
    int lane = threadIdx.x & 31;
    const ulonglong2* w2 = (const ulonglong2*)wrow;
    unsigned long long acc[NB];
#pragma unroll
    for (int b = 0; b < NB; b++) acc[b] = 0ull;
#pragma unroll
    for (int i = 0; i < P4; i++) {
        ulonglong2 w = w2[lane + 32 * i];
#pragma unroll
        for (int b = 0; b < NB; b++) { fma2(acc[b], a[b][i].x, w.x);
                                       fma2(acc[b], a[b][i].y, w.y); }
    }
    float s[NB];
#pragma unroll
    for (int b = 0; b < NB; b++) {
        float lo = __uint_as_float((unsigned)(acc[b] & 0xffffffffull));
        float hi = __uint_as_float((unsigned)(acc[b] >> 32));
        s[b] = lo + hi;
    }
#pragma unroll
    for (int off = 16; off; off >>= 1)
#pragma unroll
        for (int b = 0; b < NB; b++) s[b] += __shfl_xor_sync(0xffffffffu, s[b], off);
#pragma unroll
    for (int b = 0; b < NB; b++) out[b] = s[b];
}

// scalar warp dot (scan stage; v from smem, w from gmem)
template <int N4>
__device__ __forceinline__ float warp_dot(const float4* __restrict__ v4,
                                          const float4* __restrict__ w4) {
    int lane = threadIdx.x & 31;
    float s = 0.0f;
#pragma unroll
    for (int i = 0; i < N4 / 32; i++) {
        float4 a = v4[lane + i * 32];
        float4 b = w4[lane + i * 32];
        s += a.x * b.x + a.y * b.y + a.z * b.z + a.w * b.w;
    }
#pragma unroll
    for (int off = 16; off; off >>= 1)
        s += __shfl_xor_sync(0xffffffffu, s, off);
    return s;
}

// ============ THE CHAIN: one cluster kernel, 5 stages, 4 cluster syncs ======
__global__ void __cluster_dims__(CLUSTER_N, 1, 1) __launch_bounds__(CH_THREADS, 1)
k_chain(const float* __restrict__ x,
        const float* __restrict__ q_w,
        const float* __restrict__ in_proj_w,
        const float* __restrict__ conv_w,
        const float* __restrict__ conv_b,
        const float* __restrict__ x_proj_w,
        const float* __restrict__ dt_w,
        const float* __restrict__ dt_b,
        const float* __restrict__ Dv,
        const float* __restrict__ out_proj_w,
        const float* __restrict__ proj_w,
        const float* __restrict__ proj_b,
        float* __restrict__ out) {
    __shared__ __align__(16) float s_buf[4096];   // 16KB, reused per stage
    __shared__ float s_db[64];
    const int t = threadIdx.x;
    const int lane = t & 31;
    const int wi = t >> 5;
    const int cr = blockIdx.x;                    // == cluster_ctarank (1 cluster)
    const int gw = cr * 16 + wi;                  // 0..127 cluster-wide warp id
    const int gt = cr * CH_THREADS + t;           // 0..4095

    // ---- prefetch every downstream weight line into L2 (overlaps stage A) ----
#pragma unroll
    for (int k = 0; k < 15; k++) {
        int ln = gt + k * 4096;                   // 0..61439
        if (ln < 32768)        pf_l2(in_proj_w + (size_t)ln * 32);
        else if (ln < 49152)   pf_l2(out_proj_w + (size_t)(ln - 32768) * 32);
        else if (ln < 57344)   pf_l2(proj_w + (size_t)(ln - 49152) * 32);
        else if (ln < 59392)   pf_l2(x_proj_w + (size_t)(ln - 57344) * 32);
        else if (ln < 60416)   pf_l2(dt_w + (size_t)(ln - 59392) * 32);
        else if (ln < 60544)   pf_l2(conv_w + (size_t)(ln - 60416) * 32);
        else if (ln < 60576)   pf_l2(conv_b + (size_t)(ln - 60544) * 32);
        else if (ln < 60608)   pf_l2(dt_b + (size_t)(ln - 60576) * 32);
        else if (ln < 60640)   pf_l2(Dv + (size_t)(ln - 60608) * 32);
    }

    // ================= stage A: q = cls @ q_w.T =================
    for (int i = t; i < B_SZ * DIM; i += CH_THREADS)
        s_buf[i] = x[(size_t)(i >> 9) * N_TOK * DIM + (i & 511)];   // cls tokens
    __syncthreads();
    {
        ulonglong2 a[4][4];
        load_act<4, 4>(a, s_buf, DIM);
#pragma unroll
        for (int k = 0; k < 4; k++) {
            int r = gw + 128 * k;                 // 0..511
            float o[4];
            rows_dot<4, 4>(a, q_w + (size_t)r * DIM, o);
            if (lane == 0)
#pragma unroll
                for (int b = 0; b < 4; b++) __stcg(&g_q[b * DIM + r], o[b]);
        }
    }
    CSYNC();

    // ================= stage B: xz = q @ in_proj_w.T ; conv-tap + silu ======
    for (int i = t; i < B_SZ * DIM; i += CH_THREADS) s_buf[i] = __ldcg(&g_q[i]);
    __syncthreads();
    {
        ulonglong2 a[4][4];
        load_act<4, 4>(a, s_buf, DIM);
#pragma unroll
        for (int k = 0; k < 16; k++) {
            int j = gw + 128 * k;                 // 0..2047
            float o[4];
            rows_dot<4, 4>(a, in_proj_w + (size_t)j * DIM, o);
            if (lane == 0) {
                if (j < D_INNER) {
                    float cw = conv_w[j * 4 + 3], cb = conv_b[j];
#pragma unroll
                    for (int b = 0; b < 4; b++)
                        __stcg(&g_xs[b * D_INNER + j], siluf(o[b] * cw + cb));
                } else {
#pragma unroll
                    for (int b = 0; b < 4; b++)
                        __stcg(&g_sz[b * D_INNER + (j - D_INNER)], siluf(o[b]));
                }
            }
        }
    }
    CSYNC();

    // ================= stage C: x_dbl + delta + scan step + gate ============
    if (cr < B_SZ) {
        int b = cr;
        for (int i = t; i < D_INNER; i += CH_THREADS)
            s_buf[i] = __ldcg(&g_xs[b * D_INNER + i]);
        __syncthreads();
        // x_dbl: 64 rows of x_proj, 16 warps x 4 rows
#pragma unroll
        for (int rr = 0; rr < 4; rr++) {
            int r = wi * 4 + rr;
            float s = warp_dot<256>((const float4*)s_buf,
                                    (const float4*)(x_proj_w + (size_t)r * D_INNER));
            if (lane == 0) s_db[r] = s;
        }
        __syncthreads();

        float bc = 0.0f;
#pragma unroll
        for (int n = 0; n < D_STATE; n++)
            bc += s_db[DT_RANK + n] * s_db[DT_RANK + D_STATE + n];

        // delta pre-act: warp wi handles rows [wi*64, wi*64+64), 2 per iter
        float coef = s_db[lane];                  // DT_RANK == 32 == warp size
        float dtv0 = 0.0f, dtv1 = 0.0f;
#pragma unroll
        for (int j = 0; j < 64; j += 2) {
            int r0 = wi * 64 + j;
            float va = dt_w[r0 * DT_RANK + lane] * coef;
            float vb = dt_w[(r0 + 1) * DT_RANK + lane] * coef;
#pragma unroll
            for (int off = 16; off; off >>= 1) {
                va += __shfl_xor_sync(0xffffffffu, va, off);
                vb += __shfl_xor_sync(0xffffffffu, vb, off);
            }
            if (lane == (j >> 1)) { dtv0 = va; dtv1 = vb; }
        }
        // thread (wi,lane) owns rows r = wi*64 + 2*lane (+1)
        int r0 = wi * 64 + 2 * lane;
#pragma unroll
        for (int p = 0; p < 2; p++) {
            int r = r0 + p;
            float dtv = p ? dtv1 : dtv0;
            float delta = softplusf(dtv + dt_b[r]);
            float u = s_buf[r];
            // h0 = 0 => y = delta*u*(B.C) + u*D, gated by silu(z)
            float y = (delta * u * bc + u * Dv[r]) * __ldcg(&g_sz[b * D_INNER + r]);
            __stcg(&g_y[b * D_INNER + r], y);
        }
    }
    CSYNC();

    // ================= stage D: mixed = y @ out_proj_w.T (2 batches/pass) ===
    for (int i = t; i < B_SZ * D_INNER; i += CH_THREADS) s_buf[i] = __ldcg(&g_y[i]);
    __syncthreads();
#pragma unroll
    for (int pass = 0; pass < 2; pass++) {
        ulonglong2 a[2][8];
        load_act<8, 2>(a, s_buf + pass * 2 * D_INNER, D_INNER);
#pragma unroll
        for (int k = 0; k < 4; k++) {
            int r = gw + 128 * k;                 // 0..511
            float o[2];
            rows_dot<8, 2>(a, out_proj_w + (size_t)r * D_INNER, o);
            if (lane == 0) {
                __stcg(&g_mixed[(pass * 2 + 0) * DIM + r], o[0]);
                __stcg(&g_mixed[(pass * 2 + 1) * DIM + r], o[1]);
            }
        }
    }
    CSYNC();

    // ================= stage E: upd_cls = mixed @ proj_w.T + proj_b =========
    for (int i = t; i < B_SZ * DIM; i += CH_THREADS) s_buf[i] = __ldcg(&g_mixed[i]);
    __syncthreads();
    {
        ulonglong2 a[4][4];
        load_act<4, 4>(a, s_buf, DIM);
#pragma unroll
        for (int k = 0; k < 4; k++) {
            int r = gw + 128 * k;                 // 0..511
            float o[4];
            rows_dot<4, 4>(a, proj_w + (size_t)r * DIM, o);
            if (lane == 0) {
                float pb = proj_b[r];
#pragma unroll
                for (int b = 0; b < 4; b++)
                    out[(size_t)b * N_TOK * DIM + r] = o[b] + pb;
            }
        }
    }
}

// ============ bulk patch copy (R7-proven config) ============================
__global__ void __launch_bounds__(256) k_copy(const float4* __restrict__ x4,
                                              float4* __restrict__ o4) {
    const int pbg = 4096 * DIM / 4;              // 524288 float4 per batch
    int tid = blockIdx.x * 256 + threadIdx.x;    // 0..524287
#pragma unroll
    for (int k = 0; k < 4; k++) {
        int i = tid + k * 524288;
        int b = i / pbg;
        int off = i - b * pbg;
        int idx = b * (N_TOK * DIM / 4) + (DIM / 4) + off;   // skip cls token
        __stcs(&o4[idx], __ldcs(&x4[idx]));
    }
}

// ---------------- launch: TWO nodes only ----------------
extern "C" void kernel_launch(void* const* d_in, const int* in_sizes, int n_in,
                              void* d_out, int out_size) {
    const float* x         = (const float*)d_in[0];
    const float* q_w       = (const float*)d_in[1];
    const float* in_proj_w = (const float*)d_in[2];
    const float* conv_w    = (const float*)d_in[3];
    const float* conv_b    = (const float*)d_in[4];
    const float* x_proj_w  = (const float*)d_in[5];
    const float* dt_w      = (const float*)d_in[6];
    const float* dt_b      = (const float*)d_in[7];
    // d_in[8] = A_log (unused: h0 = 0 at the single contributing scan step)
    const float* Dv        = (const float*)d_in[9];
    const float* out_proj_w= (const float*)d_in[10];
    const float* proj_w    = (const float*)d_in[11];
    const float* proj_b    = (const float*)d_in[12];
    float* out = (float*)d_out;

    // chain: one cluster kernel (8 CTAs, hardware cluster barriers inside)
    k_chain<<<CLUSTER_N, CH_THREADS>>>(x, q_w, in_proj_w, conv_w, conv_b,
                                       x_proj_w, dt_w, dt_b, Dv,
                                       out_proj_w, proj_w, proj_b, out);
    // copy: full-bandwidth bulk passthrough
    k_copy<<<2048, 256>>>((const float4*)x, (float4*)out);
}

// round 11
// speedup vs baseline: 1.2273x; 1.2273x over previous
#include <cuda_runtime.h>
#include <cooperative_groups.h>
namespace cg = cooperative_groups;

#define DIM     512
#define D_INNER 1024
#define DT_RANK 32
#define D_STATE 16
#define B_SZ    4
#define N_TOK   4097

// ---------------- scratch (device globals, allocation-free) ----------------
__device__ __align__(16) float g_q    [B_SZ * DIM];
__device__ __align__(16) float g_xs   [B_SZ * D_INNER];
__device__ __align__(16) float g_sz   [B_SZ * D_INNER];
__device__ __align__(16) float g_db   [B_SZ * 64];     // x_dbl: dt|B|C per batch
__device__ __align__(16) float g_y    [B_SZ * D_INNER];
__device__ __align__(16) float g_mixed[B_SZ * DIM];

// ---------------- helpers ----------------
__device__ __forceinline__ float siluf(float x) { return x / (1.0f + __expf(-x)); }
__device__ __forceinline__ float softplusf(float x) {
    return (x > 20.0f) ? x : log1pf(__expf(x));
}
__device__ __forceinline__ void pf_l2(const float* p) {
    asm volatile("prefetch.global.L2 [%0];" :: "l"(p));
}

// Warp dot: activation via __ldcg (L2-coherent), weight via plain LDG.
template <int N4>
__device__ __forceinline__ float warp_dot_cg(const float4* __restrict__ v4,
                                             const float4* __restrict__ w4) {
    int lane = threadIdx.x & 31;
    float s = 0.0f;
#pragma unroll
    for (int i = 0; i < N4 / 32; i++) {
        float4 a = __ldcg(&v4[lane + i * 32]);
        float4 b = w4[lane + i * 32];
        s += a.x * b.x + a.y * b.y + a.z * b.z + a.w * b.w;
    }
#pragma unroll
    for (int off = 16; off; off >>= 1)
        s += __shfl_xor_sync(0xffffffffu, s, off);
    return s;
}

// ---------------- chain stages (shared by coop kernel + fallback) ----------
__device__ __forceinline__ void stage_xz(int gw, int nw,
                                         const float* __restrict__ in_proj_w,
                                         const float* __restrict__ conv_w,
                                         const float* __restrict__ conv_b) {
    int lane = threadIdx.x & 31;
    for (int o = gw; o < B_SZ * 2 * D_INNER; o += nw) {     // 8192 outputs
        int b = o >> 11, j = o & 2047;
        float s = warp_dot_cg<DIM / 4>((const float4*)(g_q + b * DIM),
                                       (const float4*)(in_proj_w + (size_t)j * DIM));
        if (lane == 0) {
            if (j < D_INNER) {
                // causal conv at t=0: only last tap contributes
                float v = s * conv_w[j * 4 + 3] + conv_b[j];
                __stcg(&g_xs[b * D_INNER + j], siluf(v));
            } else {
                __stcg(&g_sz[b * D_INNER + (j - D_INNER)], siluf(s));
            }
        }
    }
}

__device__ __forceinline__ void stage_scana(int gw, int nw,
                                            const float* __restrict__ x_proj_w) {
    int lane = threadIdx.x & 31;
    for (int o = gw; o < B_SZ * 64; o += nw) {              // 256 outputs
        int b = o >> 6, r = o & 63;
        float s = warp_dot_cg<D_INNER / 4>((const float4*)(g_xs + b * D_INNER),
                                           (const float4*)(x_proj_w + (size_t)r * D_INNER));
        if (lane == 0) __stcg(&g_db[b * 64 + r], s);
    }
}

__device__ __forceinline__ void stage_scanb(int gw, int nw,
                                            const float* __restrict__ dt_w,
                                            const float* __restrict__ dt_b,
                                            const float* __restrict__ Dv) {
    int lane = threadIdx.x & 31;
    for (int base = gw * 4; base < B_SZ * D_INNER; base += nw * 4) {  // 4 rows/warp
        int b = base >> 10;                                 // rows 4-aligned: same b
        // bc = dot16(B, C) for this batch (shuffle-reduced, all lanes)
        float bc = (lane < D_STATE)
            ? __ldcg(&g_db[b * 64 + DT_RANK + lane]) *
              __ldcg(&g_db[b * 64 + DT_RANK + D_STATE + lane]) : 0.0f;
#pragma unroll
        for (int off = 16; off; off >>= 1)
            bc += __shfl_xor_sync(0xffffffffu, bc, off);
        float coef = __ldcg(&g_db[b * 64 + lane]);          // dt coeffs (32)
#pragma unroll
        for (int p = 0; p < 4; p++) {
            int R = base + p;
            int r = R & 1023;
            float v = dt_w[r * DT_RANK + lane] * coef;      // coalesced row
#pragma unroll
            for (int off = 16; off; off >>= 1)
                v += __shfl_xor_sync(0xffffffffu, v, off);
            if (lane == 0) {
                float delta = softplusf(v + dt_b[r]);
                float u = __ldcg(&g_xs[R]);
                // h0 = 0 => y = delta*u*(B.C) + u*D, gated by silu(z)
                float y = (delta * u * bc + u * Dv[r]) * __ldcg(&g_sz[R]);
                __stcg(&g_y[R], y);
            }
        }
    }
}

__device__ __forceinline__ void stage_mixed(int gw, int nw,
                                            const float* __restrict__ out_proj_w) {
    int lane = threadIdx.x & 31;
    for (int o = gw; o < B_SZ * DIM; o += nw) {             // 2048 outputs
        int b = o >> 9, r = o & 511;
        float s = warp_dot_cg<D_INNER / 4>((const float4*)(g_y + b * D_INNER),
                                           (const float4*)(out_proj_w + (size_t)r * D_INNER));
        if (lane == 0) __stcg(&g_mixed[b * DIM + r], s);
    }
}

__device__ __forceinline__ void stage_out(int gw, int nw,
                                          const float* __restrict__ proj_w,
                                          const float* __restrict__ proj_b,
                                          float* __restrict__ out) {
    int lane = threadIdx.x & 31;
    for (int o = gw; o < B_SZ * DIM; o += nw) {             // 2048 outputs
        int b = o >> 9, r = o & 511;
        float s = warp_dot_cg<DIM / 4>((const float4*)(g_mixed + b * DIM),
                                       (const float4*)(proj_w + (size_t)r * DIM));
        if (lane == 0)
            out[(size_t)b * N_TOK * DIM + r] = s + proj_b[r];
    }
}

// ============ NODE 1: bulk copy + q = cls @ q_w.T + in_proj prefetch ========
#define Q_BLOCKS    256
#define COPY_BLOCKS 2048
__global__ void __launch_bounds__(256)
k_copy_q(const float* __restrict__ x,
         const float* __restrict__ q_w,
         const float* __restrict__ in_proj_w,
         float* __restrict__ out) {
    int t = threadIdx.x;
    if (blockIdx.x < Q_BLOCKS) {
        int tid = blockIdx.x * 256 + t;                     // 0..65535
        if (tid < 32768) pf_l2(in_proj_w + (size_t)tid * 32);   // 4MB -> L2
        int gw = blockIdx.x * 8 + (t >> 5);                 // 2048 warps
        int b = gw / DIM, r = gw % DIM;
        float s = warp_dot_cg<DIM / 4>((const float4*)(x + (size_t)b * N_TOK * DIM),
                                       (const float4*)(q_w + (size_t)r * DIM));
        if ((t & 31) == 0) __stcg(&g_q[b * DIM + r], s);
        return;
    }
    const float4* x4 = (const float4*)x;
    float4* o4 = (float4*)out;
    const int pbg = 4096 * DIM / 4;                         // 524288 per batch
    int tid = (blockIdx.x - Q_BLOCKS) * 256 + t;            // 0..524287
#pragma unroll
    for (int k = 0; k < 4; k++) {
        int i = tid + k * 524288;
        int b = i / pbg;
        int off = i - b * pbg;
        int idx = b * (N_TOK * DIM / 4) + (DIM / 4) + off;  // skip cls token
        __stcs(&o4[idx], __ldcs(&x4[idx]));
    }
}

// ============ NODE 2: cooperative chain (grid-wide syncs between stages) ====
#define COOP_CTAS 128
__global__ void __launch_bounds__(256)
k_chain_coop(const float* __restrict__ in_proj_w,
             const float* __restrict__ conv_w,
             const float* __restrict__ conv_b,
             const float* __restrict__ x_proj_w,
             const float* __restrict__ dt_w,
             const float* __restrict__ dt_b,
             const float* __restrict__ Dv,
             const float* __restrict__ out_proj_w,
             const float* __restrict__ proj_w,
             const float* __restrict__ proj_b,
             float* __restrict__ out) {
    int tid = blockIdx.x * 256 + threadIdx.x;               // 0..32767
    int gw = tid >> 5;                                      // 0..1023
    const int nw = (COOP_CTAS * 256) >> 5;                  // 1024 warps

    // prefetch remaining weights (27648 lines over 32768 threads)
    if (tid < 16384)       pf_l2(out_proj_w + (size_t)tid * 32);          // 2MB
    else if (tid < 24576)  pf_l2(proj_w + (size_t)(tid - 16384) * 32);    // 1MB
    else if (tid < 26624)  pf_l2(x_proj_w + (size_t)(tid - 24576) * 32);  // 256KB
    else if (tid < 27648)  pf_l2(dt_w + (size_t)(tid - 26624) * 32);      // 128KB

    cg::grid_group grid = cg::this_grid();
    stage_xz(gw, nw, in_proj_w, conv_w, conv_b);
    grid.sync();
    stage_scana(gw, nw, x_proj_w);
    grid.sync();
    stage_scanb(gw, nw, dt_w, dt_b, Dv);
    grid.sync();
    stage_mixed(gw, nw, out_proj_w);
    grid.sync();
    stage_out(gw, nw, proj_w, proj_b, out);
}

// ---------------- fallback stage kernels (if coop launch unavailable) ------
__global__ void __launch_bounds__(256) k_f_xz(const float* __restrict__ in_proj_w,
                                              const float* __restrict__ conv_w,
                                              const float* __restrict__ conv_b) {
    stage_xz((blockIdx.x * 256 + threadIdx.x) >> 5, (1024 * 256) >> 5,
             in_proj_w, conv_w, conv_b);
}
__global__ void __launch_bounds__(256) k_f_scana(const float* __restrict__ x_proj_w) {
    stage_scana((blockIdx.x * 256 + threadIdx.x) >> 5, (32 * 256) >> 5, x_proj_w);
}
__global__ void __launch_bounds__(256) k_f_scanb(const float* __restrict__ dt_w,
                                                 const float* __restrict__ dt_b,
                                                 const float* __restrict__ Dv) {
    stage_scanb((blockIdx.x * 256 + threadIdx.x) >> 5, (128 * 256) >> 5,
                dt_w, dt_b, Dv);
}
__global__ void __launch_bounds__(256) k_f_mixed(const float* __restrict__ out_proj_w) {
    stage_mixed((blockIdx.x * 256 + threadIdx.x) >> 5, (256 * 256) >> 5, out_proj_w);
}
__global__ void __launch_bounds__(256) k_f_out(const float* __restrict__ proj_w,
                                               const float* __restrict__ proj_b,
                                               float* __restrict__ out) {
    stage_out((blockIdx.x * 256 + threadIdx.x) >> 5, (256 * 256) >> 5,
              proj_w, proj_b, out);
}

// ---------------- launch: 2 nodes (copy_q, cooperative chain) --------------
extern "C" void kernel_launch(void* const* d_in, const int* in_sizes, int n_in,
                              void* d_out, int out_size) {
    const float* x         = (const float*)d_in[0];
    const float* q_w       = (const float*)d_in[1];
    const float* in_proj_w = (const float*)d_in[2];
    const float* conv_w    = (const float*)d_in[3];
    const float* conv_b    = (const float*)d_in[4];
    const float* x_proj_w  = (const float*)d_in[5];
    const float* dt_w      = (const float*)d_in[6];
    const float* dt_b      = (const float*)d_in[7];
    // d_in[8] = A_log (unused: h0 = 0 at the single contributing scan step)
    const float* Dv        = (const float*)d_in[9];
    const float* out_proj_w= (const float*)d_in[10];
    const float* proj_w    = (const float*)d_in[11];
    const float* proj_b    = (const float*)d_in[12];
    float* out = (float*)d_out;

    k_copy_q<<<Q_BLOCKS + COPY_BLOCKS, 256>>>(x, q_w, in_proj_w, out);

    // cooperative chain node (all stages, grid-wide barriers)
    const float* a0 = in_proj_w; const float* a1 = conv_w;  const float* a2 = conv_b;
    const float* a3 = x_proj_w;  const float* a4 = dt_w;    const float* a5 = dt_b;
    const float* a6 = Dv;        const float* a7 = out_proj_w;
    const float* a8 = proj_w;    const float* a9 = proj_b;  float* a10 = out;
    void* args[] = {(void*)&a0, (void*)&a1, (void*)&a2, (void*)&a3, (void*)&a4,
                    (void*)&a5, (void*)&a6, (void*)&a7, (void*)&a8, (void*)&a9,
                    (void*)&a10};
    cudaError_t e = cudaLaunchCooperativeKernel((void*)k_chain_coop,
                                                dim3(COOP_CTAS), dim3(256),
                                                args, 0, (cudaStream_t)0);
    if (e != cudaSuccess) {
        cudaGetLastError();
        // deterministic fallback: separate stage kernels (R2-like)
        k_f_xz   <<<1024, 256>>>(in_proj_w, conv_w, conv_b);
        k_f_scana<<<32,   256>>>(x_proj_w);
        k_f_scanb<<<128,  256>>>(dt_w, dt_b, Dv);
        k_f_mixed<<<256,  256>>>(out_proj_w);
        k_f_out  <<<256,  256>>>(proj_w, proj_b, out);
    }
}

// round 12
// speedup vs baseline: 1.5099x; 1.2302x over previous
#include <cuda_runtime.h>

#define DIM     512
#define D_INNER 1024
#define DT_RANK 32
#define D_STATE 16
#define B_SZ    4
#define N_TOK   4097

// ---------------- scratch (device globals, allocation-free) ----------------
__device__ __align__(16) float g_q    [B_SZ * DIM];
__device__ __align__(16) float g_xs   [B_SZ * D_INNER];
__device__ __align__(16) float g_sz   [B_SZ * D_INNER];
__device__ __align__(16) float g_db   [B_SZ * 64];
__device__ __align__(16) float g_y    [B_SZ * D_INNER];
__device__ __align__(16) float g_mixed[B_SZ * DIM];

// ---------------- helpers ----------------
__device__ __forceinline__ float siluf(float x) { return x / (1.0f + __expf(-x)); }
__device__ __forceinline__ float softplusf(float x) {
    return (x > 20.0f) ? x : log1pf(__expf(x));
}
__device__ __forceinline__ void pf_l2(const float* p) {
    asm volatile("prefetch.global.L2 [%0];" :: "l"(p));
}
// release-fence + cluster barrier + acquire-fence (cross-CTA global handoff)
#define CFENCE_SYNC() do {                                            \
    __threadfence();                                                  \
    asm volatile("barrier.cluster.arrive.aligned;" ::: "memory");     \
    asm volatile("barrier.cluster.wait.aligned;"   ::: "memory");     \
    __threadfence();                                                  \
} while (0)

// Load activation slice into registers (lane-strided float4 layout).
template <int P4>
__device__ __forceinline__ void lact_cg(float4 a[P4], const float* p) {
    int lane = threadIdx.x & 31;
    const float4* p4 = (const float4*)p;
#pragma unroll
    for (int i = 0; i < P4; i++) a[i] = __ldcg(&p4[lane + 32 * i]);
}
template <int P4>
__device__ __forceinline__ void lact(float4 a[P4], const float* p) {
    int lane = threadIdx.x & 31;
    const float4* p4 = (const float4*)p;
#pragma unroll
    for (int i = 0; i < P4; i++) a[i] = p4[lane + 32 * i];
}

// Register-activation x gmem-weight-row warp dot (result on all lanes).
template <int P4>
__device__ __forceinline__ float rdot(const float4 a[P4],
                                      const float4* __restrict__ w4) {
    int lane = threadIdx.x & 31;
    float s = 0.0f;
#pragma unroll
    for (int i = 0; i < P4; i++) {
        float4 w = w4[lane + 32 * i];
        s += a[i].x * w.x + a[i].y * w.y + a[i].z * w.z + a[i].w * w.w;
    }
#pragma unroll
    for (int off = 16; off; off >>= 1)
        s += __shfl_xor_sync(0xffffffffu, s, off);
    return s;
}

// ============ THE CHAIN: 4 clusters (1/batch) x 8 CTAs x 512 thr ============
__global__ void __cluster_dims__(8, 1, 1) __launch_bounds__(512, 1)
k_chain(const float* __restrict__ x,
        const float* __restrict__ q_w,
        const float* __restrict__ in_proj_w,
        const float* __restrict__ conv_w,
        const float* __restrict__ conv_b,
        const float* __restrict__ x_proj_w,
        const float* __restrict__ dt_w,
        const float* __restrict__ dt_b,
        const float* __restrict__ Dv,
        const float* __restrict__ out_proj_w,
        const float* __restrict__ proj_w,
        const float* __restrict__ proj_b,
        float* __restrict__ out) {
    const int t = threadIdx.x;
    const int lane = t & 31;
    const int b  = blockIdx.x >> 3;               // batch = cluster id
    const int cw = ((blockIdx.x & 7) << 4) + (t >> 5);  // warp-in-cluster 0..127

    // ---- entry prefetch: ALL weights DRAM->L2 from 16384 threads ----
    {
        int tid = blockIdx.x * 512 + t;           // 0..16383
#pragma unroll
        for (int k = 0; k < 5; k++) {
            int ln = tid + k * 16384;             // 0..81919 (need 68608)
            if (ln < 8192)        pf_l2(q_w + (size_t)ln * 32);
            else if (ln < 40960)  pf_l2(in_proj_w + (size_t)(ln - 8192) * 32);
            else if (ln < 57344)  pf_l2(out_proj_w + (size_t)(ln - 40960) * 32);
            else if (ln < 65536)  pf_l2(proj_w + (size_t)(ln - 57344) * 32);
            else if (ln < 67584)  pf_l2(x_proj_w + (size_t)(ln - 65536) * 32);
            else if (ln < 68608)  pf_l2(dt_w + (size_t)(ln - 67584) * 32);
        }
    }

    // ================= stage 1: q = cls @ q_w.T (4 rows/warp) ===============
    {
        float4 a[4];                              // cls token (512 floats)
        lact<4>(a, x + (size_t)b * N_TOK * DIM);
#pragma unroll
        for (int rr = 0; rr < 4; rr++) {
            int r = cw * 4 + rr;                  // 0..511
            float s = rdot<4>(a, (const float4*)(q_w + (size_t)r * DIM));
            if (lane == 0) __stcg(&g_q[b * DIM + r], s);
        }
    }
    CFENCE_SYNC();

    // ================= stage 2: xz = q @ in_proj.T ; conv-tap + silu ========
    {
        float4 a[4];
        lact_cg<4>(a, g_q + b * DIM);
#pragma unroll
        for (int rr = 0; rr < 16; rr++) {
            int j = cw * 16 + rr;                 // 0..2047
            float s = rdot<4>(a, (const float4*)(in_proj_w + (size_t)j * DIM));
            if (lane == 0) {
                if (j < D_INNER) {
                    // causal conv at t=0: only last tap contributes
                    float v = s * conv_w[j * 4 + 3] + conv_b[j];
                    __stcg(&g_xs[b * D_INNER + j], siluf(v));
                } else {
                    __stcg(&g_sz[b * D_INNER + (j - D_INNER)], siluf(s));
                }
            }
        }
    }
    CFENCE_SYNC();

    // ================= stage 3: x_dbl = xs @ x_proj.T (1 row/warp, 64) ======
    if (cw < 64) {
        float4 a[8];                              // xs (1024 floats)
        lact_cg<8>(a, g_xs + b * D_INNER);
        float s = rdot<8>(a, (const float4*)(x_proj_w + (size_t)cw * D_INNER));
        if (lane == 0) __stcg(&g_db[b * 64 + cw], s);
    }
    CFENCE_SYNC();

    // ================= stage 4: delta + scan step + gate (8 rows/warp) ======
    {
        // bc = dot(B, C) over 16 states (all lanes end with the sum)
        float bc = (lane < D_STATE)
            ? __ldcg(&g_db[b * 64 + DT_RANK + lane]) *
              __ldcg(&g_db[b * 64 + DT_RANK + D_STATE + lane]) : 0.0f;
#pragma unroll
        for (int off = 16; off; off >>= 1)
            bc += __shfl_xor_sync(0xffffffffu, bc, off);
        float coef = __ldcg(&g_db[b * 64 + lane]);   // dt coeffs (DT_RANK==32)
#pragma unroll
        for (int rr = 0; rr < 8; rr++) {
            int r = cw * 8 + rr;                  // 0..1023
            float v = dt_w[r * DT_RANK + lane] * coef;   // coalesced 128B row
#pragma unroll
            for (int off = 16; off; off >>= 1)
                v += __shfl_xor_sync(0xffffffffu, v, off);
            if (lane == 0) {
                float delta = softplusf(v + dt_b[r]);
                float u = __ldcg(&g_xs[b * D_INNER + r]);
                // h0 = 0 => y = delta*u*(B.C) + u*D, gated by silu(z)
                float y = (delta * u * bc + u * Dv[r]) *
                          __ldcg(&g_sz[b * D_INNER + r]);
                __stcg(&g_y[b * D_INNER + r], y);
            }
        }
    }
    CFENCE_SYNC();

    // ================= stage 5: mixed = y @ out_proj.T (4 rows/warp) ========
    {
        float4 a[8];
        lact_cg<8>(a, g_y + b * D_INNER);
#pragma unroll
        for (int rr = 0; rr < 4; rr++) {
            int r = cw * 4 + rr;                  // 0..511
            float s = rdot<8>(a, (const float4*)(out_proj_w + (size_t)r * D_INNER));
            if (lane == 0) __stcg(&g_mixed[b * DIM + r], s);
        }
    }
    CFENCE_SYNC();

    // ================= stage 6: upd_cls = mixed @ proj.T + proj_b ===========
    {
        float4 a[4];
        lact_cg<4>(a, g_mixed + b * DIM);
#pragma unroll
        for (int rr = 0; rr < 4; rr++) {
            int r = cw * 4 + rr;                  // 0..511
            float s = rdot<4>(a, (const float4*)(proj_w + (size_t)r * DIM));
            if (lane == 0)
                out[(size_t)b * N_TOK * DIM + r] = s + proj_b[r];
        }
    }
}

// ============ bulk patch copy (R7-proven config) ============================
__global__ void __launch_bounds__(256) k_copy(const float4* __restrict__ x4,
                                              float4* __restrict__ o4) {
    const int pbg = 4096 * DIM / 4;              // 524288 float4 per batch
    int tid = blockIdx.x * 256 + threadIdx.x;    // 0..524287
#pragma unroll
    for (int k = 0; k < 4; k++) {
        int i = tid + k * 524288;
        int b = i / pbg;
        int off = i - b * pbg;
        int idx = b * (N_TOK * DIM / 4) + (DIM / 4) + off;   // skip cls token
        __stcs(&o4[idx], __ldcs(&x4[idx]));
    }
}

// ---------------- fallback stage kernels (cluster launch failure only) -----
template <int N4>
__device__ __forceinline__ float wdot_cg(const float4* v4, const float4* w4) {
    int lane = threadIdx.x & 31;
    float s = 0.0f;
#pragma unroll
    for (int i = 0; i < N4 / 32; i++) {
        float4 a = __ldcg(&v4[lane + i * 32]);
        float4 b = w4[lane + i * 32];
        s += a.x * b.x + a.y * b.y + a.z * b.z + a.w * b.w;
    }
#pragma unroll
    for (int off = 16; off; off >>= 1)
        s += __shfl_xor_sync(0xffffffffu, s, off);
    return s;
}
__global__ void __launch_bounds__(256) k_f_q(const float* x, const float* q_w) {
    int gw = (blockIdx.x * 256 + threadIdx.x) >> 5;
    int b = gw / DIM, r = gw % DIM;
    float s = wdot_cg<DIM/4>((const float4*)(x + (size_t)b * N_TOK * DIM),
                             (const float4*)(q_w + (size_t)r * DIM));
    if ((threadIdx.x & 31) == 0) __stcg(&g_q[b * DIM + r], s);
}
__global__ void __launch_bounds__(256) k_f_xz(const float* in_proj_w,
                                              const float* conv_w, const float* conv_b) {
    int o = (blockIdx.x * 256 + threadIdx.x) >> 5;
    int b = o >> 11, j = o & 2047;
    float s = wdot_cg<DIM/4>((const float4*)(g_q + b * DIM),
                             (const float4*)(in_proj_w + (size_t)j * DIM));
    if ((threadIdx.x & 31) == 0) {
        if (j < D_INNER) __stcg(&g_xs[b*D_INNER+j], siluf(s*conv_w[j*4+3]+conv_b[j]));
        else             __stcg(&g_sz[b*D_INNER+(j-D_INNER)], siluf(s));
    }
}
__global__ void __launch_bounds__(256) k_f_scana(const float* x_proj_w) {
    int o = (blockIdx.x * 256 + threadIdx.x) >> 5;
    int b = o >> 6, r = o & 63;
    float s = wdot_cg<D_INNER/4>((const float4*)(g_xs + b * D_INNER),
                                 (const float4*)(x_proj_w + (size_t)r * D_INNER));
    if ((threadIdx.x & 31) == 0) __stcg(&g_db[b * 64 + r], s);
}
__global__ void __launch_bounds__(256) k_f_scanb(const float* dt_w,
                                                 const float* dt_b, const float* Dv) {
    int lane = threadIdx.x & 31;
    int gw = (blockIdx.x * 256 + threadIdx.x) >> 5;     // 0..1023
    int R = gw * 4;                                     // 4 rows/warp
    int b = R >> 10;
    float bc = (lane < D_STATE)
        ? __ldcg(&g_db[b*64+DT_RANK+lane]) * __ldcg(&g_db[b*64+DT_RANK+D_STATE+lane]) : 0.0f;
#pragma unroll
    for (int off = 16; off; off >>= 1) bc += __shfl_xor_sync(0xffffffffu, bc, off);
    float coef = __ldcg(&g_db[b * 64 + lane]);
#pragma unroll
    for (int p = 0; p < 4; p++) {
        int r = (R + p) & 1023;
        float v = dt_w[r * DT_RANK + lane] * coef;
#pragma unroll
        for (int off = 16; off; off >>= 1) v += __shfl_xor_sync(0xffffffffu, v, off);
        if (lane == 0) {
            float delta = softplusf(v + dt_b[r]);
            float u = __ldcg(&g_xs[R + p]);
            __stcg(&g_y[R + p], (delta*u*bc + u*Dv[r]) * __ldcg(&g_sz[R + p]));
        }
    }
}
__global__ void __launch_bounds__(256) k_f_mixed(const float* out_proj_w) {
    int o = (blockIdx.x * 256 + threadIdx.x) >> 5;
    int b = o >> 9, r = o & 511;
    float s = wdot_cg<D_INNER/4>((const float4*)(g_y + b * D_INNER),
                                 (const float4*)(out_proj_w + (size_t)r * D_INNER));
    if ((threadIdx.x & 31) == 0) __stcg(&g_mixed[b * DIM + r], s);
}
__global__ void __launch_bounds__(256) k_f_out(const float* proj_w,
                                               const float* proj_b, float* out) {
    int o = (blockIdx.x * 256 + threadIdx.x) >> 5;
    int b = o >> 9, r = o & 511;
    float s = wdot_cg<DIM/4>((const float4*)(g_mixed + b * DIM),
                             (const float4*)(proj_w + (size_t)r * DIM));
    if ((threadIdx.x & 31) == 0) out[(size_t)b * N_TOK * DIM + r] = s + proj_b[r];
}

// ---------------- launch: 2 nodes (cluster chain, then copy) ---------------
extern "C" void kernel_launch(void* const* d_in, const int* in_sizes, int n_in,
                              void* d_out, int out_size) {
    const float* x         = (const float*)d_in[0];
    const float* q_w       = (const float*)d_in[1];
    const float* in_proj_w = (const float*)d_in[2];
    const float* conv_w    = (const float*)d_in[3];
    const float* conv_b    = (const float*)d_in[4];
    const float* x_proj_w  = (const float*)d_in[5];
    const float* dt_w      = (const float*)d_in[6];
    const float* dt_b      = (const float*)d_in[7];
    // d_in[8] = A_log (unused: h0 = 0 at the single contributing scan step)
    const float* Dv        = (const float*)d_in[9];
    const float* out_proj_w= (const float*)d_in[10];
    const float* proj_w    = (const float*)d_in[11];
    const float* proj_b    = (const float*)d_in[12];
    float* out = (float*)d_out;

    // chain: one node, 4 clusters (1 per batch) x 8 CTAs x 512 threads
    k_chain<<<32, 512>>>(x, q_w, in_proj_w, conv_w, conv_b, x_proj_w,
                         dt_w, dt_b, Dv, out_proj_w, proj_w, proj_b, out);
    if (cudaGetLastError() != cudaSuccess) {
        // fallback: proven multi-kernel chain
        k_f_q    <<<256,  256>>>(x, q_w);
        k_f_xz   <<<1024, 256>>>(in_proj_w, conv_w, conv_b);
        k_f_scana<<<32,   256>>>(x_proj_w);
        k_f_scanb<<<128,  256>>>(dt_w, dt_b, Dv);
        k_f_mixed<<<256,  256>>>(out_proj_w);
        k_f_out  <<<256,  256>>>(proj_w, proj_b, out);
    }

    // copy: full-bandwidth bulk passthrough
    k_copy<<<2048, 256>>>((const float4*)x, (float4*)out);
}

// round 13
// speedup vs baseline: 1.6036x; 1.0621x over previous
#include <cuda_runtime.h>

#define DIM     512
#define D_INNER 1024
#define DT_RANK 32
#define D_STATE 16
#define B_SZ    4
#define N_TOK   4097

// ---------------- scratch (device globals, allocation-free) ----------------
__device__ __align__(16) float g_q    [B_SZ * DIM];
__device__ __align__(16) float g_xs   [B_SZ * D_INNER];
__device__ __align__(16) float g_sz   [B_SZ * D_INNER];
__device__ __align__(16) float g_db   [B_SZ * 64];
__device__ __align__(16) float g_y    [B_SZ * D_INNER];
__device__ __align__(16) float g_mixed[B_SZ * DIM];
__device__ float g_dummy;                      // sink for warm reads

// ---------------- helpers ----------------
__device__ __forceinline__ float siluf(float x) { return x / (1.0f + __expf(-x)); }
__device__ __forceinline__ float softplusf(float x) {
    return (x > 20.0f) ? x : log1pf(__expf(x));
}
// release-fence + cluster barrier + acquire-fence (cross-CTA global handoff)
#define CFENCE_SYNC() do {                                            \
    __threadfence();                                                  \
    asm volatile("barrier.cluster.arrive.aligned;" ::: "memory");     \
    asm volatile("barrier.cluster.wait.aligned;"   ::: "memory");     \
    __threadfence();                                                  \
} while (0)

template <int P4>
__device__ __forceinline__ void lact_cg(float4 a[P4], const float* p) {
    int lane = threadIdx.x & 31;
    const float4* p4 = (const float4*)p;
#pragma unroll
    for (int i = 0; i < P4; i++) a[i] = __ldcg(&p4[lane + 32 * i]);
}

// Register-activation x gmem-weight-row warp dot (result on all lanes).
template <int P4>
__device__ __forceinline__ float rdot(const float4 a[P4],
                                      const float4* __restrict__ w4) {
    int lane = threadIdx.x & 31;
    float s = 0.0f;
#pragma unroll
    for (int i = 0; i < P4; i++) {
        float4 w = w4[lane + 32 * i];
        s += a[i].x * w.x + a[i].y * w.y + a[i].z * w.z + a[i].w * w.w;
    }
#pragma unroll
    for (int off = 16; off; off >>= 1)
        s += __shfl_xor_sync(0xffffffffu, s, off);
    return s;
}

// scalar warp dot (gmem activation via __ldcg + gmem weight)
template <int N4>
__device__ __forceinline__ float wdot_cg(const float4* v4, const float4* w4) {
    int lane = threadIdx.x & 31;
    float s = 0.0f;
#pragma unroll
    for (int i = 0; i < N4 / 32; i++) {
        float4 a = __ldcg(&v4[lane + i * 32]);
        float4 b = w4[lane + i * 32];
        s += a.x * b.x + a.y * b.y + a.z * b.z + a.w * b.w;
    }
#pragma unroll
    for (int off = 16; off; off >>= 1)
        s += __shfl_xor_sync(0xffffffffu, s, off);
    return s;
}

// ============ NODE 1: q matvec + weight warm (REAL reads) + bulk copy =======
#define Q_BLOCKS    256
#define WARM_BLOCKS 128
#define COPY_BLOCKS 2048
__global__ void __launch_bounds__(256)
k_warm_copy_q(const float* __restrict__ x,
              const float* __restrict__ q_w,
              const float* __restrict__ in_proj_w,
              const float* __restrict__ x_proj_w,
              const float* __restrict__ dt_w,
              const float* __restrict__ out_proj_w,
              const float* __restrict__ proj_w,
              float* __restrict__ out) {
    int t = threadIdx.x;
    unsigned bx = blockIdx.x;

    if (bx < Q_BLOCKS) {
        // q = cls @ q_w.T : 2048 warps, 1 row each (R2-proven)
        int gw = bx * 8 + (t >> 5);
        int b = gw / DIM, r = gw % DIM;
        float s = wdot_cg<DIM / 4>((const float4*)(x + (size_t)b * N_TOK * DIM),
                                   (const float4*)(q_w + (size_t)r * DIM));
        if ((t & 31) == 0) __stcg(&g_q[b * DIM + r], s);
        return;
    }
    if (bx < Q_BLOCKS + WARM_BLOCKS) {
        // REAL L2-warming reads: one float per 32B sector of every weight.
        // sectors: in_proj 131072 | out_proj 65536 | proj 32768 | x_proj 8192 | dt_w 4096
        int tid = (bx - Q_BLOCKS) * 256 + t;          // 0..32767
        float acc = 0.0f;
#pragma unroll
        for (int k = 0; k < 8; k++) {
            int sc = tid + k * 32768;                 // 0..262143 (need 241664)
            if (sc < 131072)       acc += __ldcg(in_proj_w + (size_t)sc * 8);
            else if (sc < 196608)  acc += __ldcg(out_proj_w + (size_t)(sc - 131072) * 8);
            else if (sc < 229376)  acc += __ldcg(proj_w + (size_t)(sc - 196608) * 8);
            else if (sc < 237568)  acc += __ldcg(x_proj_w + (size_t)(sc - 229376) * 8);
            else if (sc < 241664)  acc += __ldcg(dt_w + (size_t)(sc - 237568) * 8);
        }
        if (acc == 1.2345e37f) g_dummy = acc;         // keep loads alive
        return;
    }
    // bulk patch copy (R7-proven config; streaming, evict-first)
    const float4* x4 = (const float4*)x;
    float4* o4 = (float4*)out;
    const int pbg = 4096 * DIM / 4;                   // 524288 per batch
    int tid = (bx - Q_BLOCKS - WARM_BLOCKS) * 256 + t;
#pragma unroll
    for (int k = 0; k < 4; k++) {
        int i = tid + k * 524288;
        int b = i / pbg;
        int off = i - b * pbg;
        int idx = b * (N_TOK * DIM / 4) + (DIM / 4) + off;  // skip cls token
        __stcs(&o4[idx], __ldcs(&x4[idx]));
    }
}

// ============ NODE 2: cluster chain, all weights L2-warm ====================
__global__ void __cluster_dims__(8, 1, 1) __launch_bounds__(512, 1)
k_chain(const float* __restrict__ in_proj_w,
        const float* __restrict__ conv_w,
        const float* __restrict__ conv_b,
        const float* __restrict__ x_proj_w,
        const float* __restrict__ dt_w,
        const float* __restrict__ dt_b,
        const float* __restrict__ Dv,
        const float* __restrict__ out_proj_w,
        const float* __restrict__ proj_w,
        const float* __restrict__ proj_b,
        float* __restrict__ out) {
    const int t = threadIdx.x;
    const int lane = t & 31;
    const int b  = blockIdx.x >> 3;               // batch = cluster id
    const int cw = ((blockIdx.x & 7) << 4) + (t >> 5);  // warp-in-cluster 0..127

    // ================= stage 1: xz = q @ in_proj.T ; conv-tap + silu ========
    {
        float4 a[4];
        lact_cg<4>(a, g_q + b * DIM);
#pragma unroll
        for (int rr = 0; rr < 16; rr++) {
            int j = cw * 16 + rr;                 // 0..2047
            float s = rdot<4>(a, (const float4*)(in_proj_w + (size_t)j * DIM));
            if (lane == 0) {
                if (j < D_INNER) {
                    // causal conv at t=0: only last tap contributes
                    float v = s * conv_w[j * 4 + 3] + conv_b[j];
                    __stcg(&g_xs[b * D_INNER + j], siluf(v));
                } else {
                    __stcg(&g_sz[b * D_INNER + (j - D_INNER)], siluf(s));
                }
            }
        }
    }
    CFENCE_SYNC();

    // ================= stage 2: x_dbl = xs @ x_proj.T (1 row/warp, 64) ======
    if (cw < 64) {
        float4 a[8];                              // xs (1024 floats)
        lact_cg<8>(a, g_xs + b * D_INNER);
        float s = rdot<8>(a, (const float4*)(x_proj_w + (size_t)cw * D_INNER));
        if (lane == 0) __stcg(&g_db[b * 64 + cw], s);
    }
    CFENCE_SYNC();

    // ================= stage 3: delta + scan step + gate (8 rows/warp) ======
    {
        float bc = (lane < D_STATE)
            ? __ldcg(&g_db[b * 64 + DT_RANK + lane]) *
              __ldcg(&g_db[b * 64 + DT_RANK + D_STATE + lane]) : 0.0f;
#pragma unroll
        for (int off = 16; off; off >>= 1)
            bc += __shfl_xor_sync(0xffffffffu, bc, off);
        float coef = __ldcg(&g_db[b * 64 + lane]);   // dt coeffs (DT_RANK==32)
#pragma unroll
        for (int rr = 0; rr < 8; rr++) {
            int r = cw * 8 + rr;                  // 0..1023
            float v = dt_w[r * DT_RANK + lane] * coef;   // coalesced 128B row
#pragma unroll
            for (int off = 16; off; off >>= 1)
                v += __shfl_xor_sync(0xffffffffu, v, off);
            if (lane == 0) {
                float delta = softplusf(v + dt_b[r]);
                float u = __ldcg(&g_xs[b * D_INNER + r]);
                // h0 = 0 => y = delta*u*(B.C) + u*D, gated by silu(z)
                float y = (delta * u * bc + u * Dv[r]) *
                          __ldcg(&g_sz[b * D_INNER + r]);
                __stcg(&g_y[b * D_INNER + r], y);
            }
        }
    }
    CFENCE_SYNC();

    // ================= stage 4: mixed = y @ out_proj.T (4 rows/warp) ========
    {
        float4 a[8];
        lact_cg<8>(a, g_y + b * D_INNER);
#pragma unroll
        for (int rr = 0; rr < 4; rr++) {
            int r = cw * 4 + rr;                  // 0..511
            float s = rdot<8>(a, (const float4*)(out_proj_w + (size_t)r * D_INNER));
            if (lane == 0) __stcg(&g_mixed[b * DIM + r], s);
        }
    }
    CFENCE_SYNC();

    // ================= stage 5: upd_cls = mixed @ proj.T + proj_b ===========
    {
        float4 a[4];
        lact_cg<4>(a, g_mixed + b * DIM);
#pragma unroll
        for (int rr = 0; rr < 4; rr++) {
            int r = cw * 4 + rr;                  // 0..511
            float s = rdot<4>(a, (const float4*)(proj_w + (size_t)r * DIM));
            if (lane == 0)
                out[(size_t)b * N_TOK * DIM + r] = s + proj_b[r];
        }
    }
}

// ---------------- fallback stage kernels (cluster launch failure only) -----
__global__ void __launch_bounds__(256) k_f_xz(const float* in_proj_w,
                                              const float* conv_w, const float* conv_b) {
    int o = (blockIdx.x * 256 + threadIdx.x) >> 5;
    int b = o >> 11, j = o & 2047;
    float s = wdot_cg<DIM/4>((const float4*)(g_q + b * DIM),
                             (const float4*)(in_proj_w + (size_t)j * DIM));
    if ((threadIdx.x & 31) == 0) {
        if (j < D_INNER) __stcg(&g_xs[b*D_INNER+j], siluf(s*conv_w[j*4+3]+conv_b[j]));
        else             __stcg(&g_sz[b*D_INNER+(j-D_INNER)], siluf(s));
    }
}
__global__ void __launch_bounds__(256) k_f_scana(const float* x_proj_w) {
    int o = (blockIdx.x * 256 + threadIdx.x) >> 5;
    int b = o >> 6, r = o & 63;
    float s = wdot_cg<D_INNER/4>((const float4*)(g_xs + b * D_INNER),
                                 (const float4*)(x_proj_w + (size_t)r * D_INNER));
    if ((threadIdx.x & 31) == 0) __stcg(&g_db[b * 64 + r], s);
}
__global__ void __launch_bounds__(256) k_f_scanb(const float* dt_w,
                                                 const float* dt_b, const float* Dv) {
    int lane = threadIdx.x & 31;
    int gw = (blockIdx.x * 256 + threadIdx.x) >> 5;     // 0..1023
    int R = gw * 4;                                     // 4 rows/warp
    int b = R >> 10;
    float bc = (lane < D_STATE)
        ? __ldcg(&g_db[b*64+DT_RANK+lane]) * __ldcg(&g_db[b*64+DT_RANK+D_STATE+lane]) : 0.0f;
#pragma unroll
    for (int off = 16; off; off >>= 1) bc += __shfl_xor_sync(0xffffffffu, bc, off);
    float coef = __ldcg(&g_db[b * 64 + lane]);
#pragma unroll
    for (int p = 0; p < 4; p++) {
        int r = (R + p) & 1023;
        float v = dt_w[r * DT_RANK + lane] * coef;
#pragma unroll
        for (int off = 16; off; off >>= 1) v += __shfl_xor_sync(0xffffffffu, v, off);
        if (lane == 0) {
            float delta = softplusf(v + dt_b[r]);
            float u = __ldcg(&g_xs[R + p]);
            __stcg(&g_y[R + p], (delta*u*bc + u*Dv[r]) * __ldcg(&g_sz[R + p]));
        }
    }
}
__global__ void __launch_bounds__(256) k_f_mixed(const float* out_proj_w) {
    int o = (blockIdx.x * 256 + threadIdx.x) >> 5;
    int b = o >> 9, r = o & 511;
    float s = wdot_cg<D_INNER/4>((const float4*)(g_y + b * D_INNER),
                                 (const float4*)(out_proj_w + (size_t)r * D_INNER));
    if ((threadIdx.x & 31) == 0) __stcg(&g_mixed[b * DIM + r], s);
}
__global__ void __launch_bounds__(256) k_f_out(const float* proj_w,
                                               const float* proj_b, float* out) {
    int o = (blockIdx.x * 256 + threadIdx.x) >> 5;
    int b = o >> 9, r = o & 511;
    float s = wdot_cg<DIM/4>((const float4*)(g_mixed + b * DIM),
                             (const float4*)(proj_w + (size_t)r * DIM));
    if ((threadIdx.x & 31) == 0) out[(size_t)b * N_TOK * DIM + r] = s + proj_b[r];
}

// ---------------- launch: 2 nodes (warm+copy+q, then cluster chain) --------
extern "C" void kernel_launch(void* const* d_in, const int* in_sizes, int n_in,
                              void* d_out, int out_size) {
    const float* x         = (const float*)d_in[0];
    const float* q_w       = (const float*)d_in[1];
    const float* in_proj_w = (const float*)d_in[2];
    const float* conv_w    = (const float*)d_in[3];
    const float* conv_b    = (const float*)d_in[4];
    const float* x_proj_w  = (const float*)d_in[5];
    const float* dt_w      = (const float*)d_in[6];
    const float* dt_b      = (const float*)d_in[7];
    // d_in[8] = A_log (unused: h0 = 0 at the single contributing scan step)
    const float* Dv        = (const float*)d_in[9];
    const float* out_proj_w= (const float*)d_in[10];
    const float* proj_w    = (const float*)d_in[11];
    const float* proj_b    = (const float*)d_in[12];
    float* out = (float*)d_out;

    // node 1: copy + q + REAL weight-warming reads (wide, full DRAM MLP)
    k_warm_copy_q<<<Q_BLOCKS + WARM_BLOCKS + COPY_BLOCKS, 256>>>(
        x, q_w, in_proj_w, x_proj_w, dt_w, out_proj_w, proj_w, out);

    // node 2: cluster chain on L2-warm weights (cheap hardware barriers)
    k_chain<<<32, 512>>>(in_proj_w, conv_w, conv_b, x_proj_w, dt_w, dt_b,
                         Dv, out_proj_w, proj_w, proj_b, out);
    if (cudaGetLastError() != cudaSuccess) {
        // fallback: proven multi-kernel chain
        k_f_xz   <<<1024, 256>>>(in_proj_w, conv_w, conv_b);
        k_f_scana<<<32,   256>>>(x_proj_w);
        k_f_scanb<<<128,  256>>>(dt_w, dt_b, Dv);
        k_f_mixed<<<256,  256>>>(out_proj_w);
        k_f_out  <<<256,  256>>>(proj_w, proj_b, out);
    }
}

// round 14
// speedup vs baseline: 1.9410x; 1.2104x over previous
#include <cuda_runtime.h>

#define DIM     512
#define D_INNER 1024
#define DT_RANK 32
#define D_STATE 16
#define B_SZ    4
#define N_TOK   4097

// ---------------- scratch (device globals, allocation-free) ----------------
__device__ __align__(16) float g_q    [B_SZ * DIM];
__device__ __align__(16) float g_xs   [B_SZ * D_INNER];
__device__ __align__(16) float g_sz   [B_SZ * D_INNER];
__device__ __align__(16) float g_y    [B_SZ * D_INNER];
__device__ __align__(16) float g_mixed[B_SZ * DIM];

// ---------------- helpers ----------------
__device__ __forceinline__ float siluf(float x) { return x / (1.0f + __expf(-x)); }
__device__ __forceinline__ float softplusf(float x) {
    return (x > 20.0f) ? x : log1pf(__expf(x));
}
__device__ __forceinline__ void pf_l2(const float* p) {
    asm volatile("prefetch.global.L2 [%0];" :: "l"(p));
}

// Warp-collective dot of two length-(N4*4) float vectors (float4 reads).
template <int N4>
__device__ __forceinline__ float warp_dot(const float4* __restrict__ v4,
                                          const float4* __restrict__ w4) {
    int lane = threadIdx.x & 31;
    float s = 0.0f;
#pragma unroll
    for (int i = 0; i < N4 / 32; i++) {
        float4 a = v4[lane + i * 32];
        float4 b = w4[lane + i * 32];
        s += a.x * b.x + a.y * b.y + a.z * b.z + a.w * b.w;
    }
#pragma unroll
    for (int off = 16; off; off >>= 1)
        s += __shfl_xor_sync(0xffffffffu, s, off);
    return s;
}

// ============ MAIN-STREAM NODE: q matvec + bulk patch copy ==================
// Blocks [0,256): q = cls @ q_w.T (2048 warps, 1 row each) + in_proj prefetch.
// Blocks [256, 256+2048): streaming copy (R7-proven config).
#define Q_BLOCKS    256
#define COPY_BLOCKS 2048
__global__ void __launch_bounds__(256)
k_copy_q(const float* __restrict__ x,
         const float* __restrict__ q_w,
         const float* __restrict__ in_proj_w,
         float* __restrict__ out) {
    int t = threadIdx.x;
    if (blockIdx.x < Q_BLOCKS) {
        int tid = blockIdx.x * 256 + t;              // 0..65535
        if (tid < 32768) pf_l2(in_proj_w + (size_t)tid * 32);    // 4MB -> L2
        int gw = blockIdx.x * 8 + (t >> 5);          // 0..2047
        int b = gw / DIM, r = gw % DIM;
        float s = warp_dot<DIM / 4>((const float4*)(x + (size_t)b * N_TOK * DIM),
                                    (const float4*)(q_w + (size_t)r * DIM));
        if ((t & 31) == 0) g_q[b * DIM + r] = s;
        return;
    }
    const float4* x4 = (const float4*)x;
    float4* o4 = (float4*)out;
    const int pbg = 4096 * DIM / 4;                  // 524288 float4 per batch
    int tid = (blockIdx.x - Q_BLOCKS) * 256 + t;     // 0..524287
#pragma unroll
    for (int k = 0; k < 4; k++) {
        int i = tid + k * 524288;
        int b = i / pbg;
        int off = i - b * pbg;
        int idx = b * (N_TOK * DIM / 4) + (DIM / 4) + off;   // skip cls token
        __stcs(&o4[idx], __ldcs(&x4[idx]));
    }
}

// ============ K2: xz = q @ in_proj_w.T ; conv-tap + silu ====================
// 1024 blocks x 8 warps x 1 output = 8192 outputs.
__global__ void __launch_bounds__(256) k_xz(const float* __restrict__ in_proj_w,
                                            const float* __restrict__ conv_w,
                                            const float* __restrict__ conv_b,
                                            const float* __restrict__ x_proj_w,
                                            const float* __restrict__ dt_w,
                                            const float* __restrict__ out_proj_w) {
    int t = threadIdx.x, wi = t >> 5, lane = t & 31;
    int tid = blockIdx.x * 256 + t;              // 0..262143
    // prefetch what K3/K4 need next: out_proj (16384 lines), x_proj (2048), dt_w (1024)
    if (tid < 16384)       pf_l2(out_proj_w + (size_t)tid * 32);
    else if (tid < 18432)  pf_l2(x_proj_w + (size_t)(tid - 16384) * 32);
    else if (tid < 19456)  pf_l2(dt_w + (size_t)(tid - 18432) * 32);

    int o = blockIdx.x * 8 + wi;                 // 0..8191
    int b = o / (2 * D_INNER), j = o % (2 * D_INNER);
    float s = warp_dot<DIM / 4>((const float4*)(g_q + b * DIM),
                                (const float4*)(in_proj_w + (size_t)j * DIM));
    if (lane == 0) {
        if (j < D_INNER) {
            // causal conv at t=0: only last tap contributes
            float v = s * conv_w[j * 4 + 3] + conv_b[j];
            g_xs[b * D_INNER + j] = siluf(v);
        } else {
            g_sz[b * D_INNER + (j - D_INNER)] = siluf(s);
        }
    }
}

// ============ K3: x_dbl + delta + first-step scan + gate (1 block/batch) ====
__global__ void __launch_bounds__(1024) k_scan(const float* __restrict__ x_proj_w,
                                               const float* __restrict__ dt_w,
                                               const float* __restrict__ dt_b,
                                               const float* __restrict__ Dv,
                                               const float* __restrict__ proj_w) {
    __shared__ __align__(16) float s_xs[D_INNER];
    __shared__ float s_db[DT_RANK + 2 * D_STATE];    // 64
    int b = blockIdx.x, t = threadIdx.x;
    int lane = t & 31, w = t >> 5;
    // prefetch proj_w (8192 lines) for K5 while we compute
    int gid = blockIdx.x * 1024 + t;             // 0..4095
    pf_l2(proj_w + (size_t)(2 * gid) * 32);
    pf_l2(proj_w + (size_t)(2 * gid + 1) * 32);

    s_xs[t] = g_xs[b * D_INNER + t];
    __syncthreads();

    // 64 rows of x_proj: 32 warps x 2 rows (coalesced float4 reads)
#pragma unroll
    for (int rr = 0; rr < 2; rr++) {
        int r = w * 2 + rr;
        float s = warp_dot<D_INNER / 4>((const float4*)s_xs,
                                        (const float4*)(x_proj_w + (size_t)r * D_INNER));
        if (lane == 0) s_db[r] = s;
    }
    __syncthreads();

    // delta pre-act: warp w handles rows [w*32, w*32+32), coalesced row loads
    float coef = s_db[lane];   // dt coefficient k = lane (DT_RANK == 32)
    float dtv = 0.0f;
#pragma unroll
    for (int rr = 0; rr < 32; rr++) {
        int r = w * 32 + rr;
        float v = dt_w[r * DT_RANK + lane] * coef;
#pragma unroll
        for (int off = 16; off; off >>= 1)
            v += __shfl_xor_sync(0xffffffffu, v, off);
        if (lane == rr) dtv = v;   // thread t = w*32+rr owns row t
    }
    float delta = softplusf(dtv + dt_b[t]);

    float bc = 0.0f;
#pragma unroll
    for (int n = 0; n < D_STATE; n++)
        bc += s_db[DT_RANK + n] * s_db[DT_RANK + D_STATE + n];

    float u = s_xs[t];
    // h0 = 0 => y = delta*u*(B.C) + u*D, gated by silu(z)
    g_y[b * D_INNER + t] = (delta * u * bc + u * Dv[t]) * g_sz[b * D_INNER + t];
}

// ============ K4: mixed = y @ out_proj_w.T ==================================
// 256 blocks x 8 warps x 1 output = 2048 outputs.
__global__ void __launch_bounds__(256) k_mixed(const float* __restrict__ out_proj_w) {
    int t = threadIdx.x, wi = t >> 5, lane = t & 31;
    int o = blockIdx.x * 8 + wi;
    int b = o / DIM, r = o % DIM;
    float s = warp_dot<D_INNER / 4>((const float4*)(g_y + b * D_INNER),
                                    (const float4*)(out_proj_w + (size_t)r * D_INNER));
    if (lane == 0) g_mixed[b * DIM + r] = s;
}

// ============ K5: upd_cls = mixed @ proj_w.T + proj_b -> out[:,0,:] =========
// 256 blocks x 8 warps x 1 output = 2048 outputs.
__global__ void __launch_bounds__(256) k_out(const float* __restrict__ proj_w,
                                             const float* __restrict__ proj_b,
                                             float* __restrict__ out) {
    int t = threadIdx.x, wi = t >> 5, lane = t & 31;
    int o = blockIdx.x * 8 + wi;
    int b = o / DIM, r = o % DIM;
    float s = warp_dot<DIM / 4>((const float4*)(g_mixed + b * DIM),
                                (const float4*)(proj_w + (size_t)r * DIM));
    if (lane == 0)
        out[(size_t)b * N_TOK * DIM + r] = s + proj_b[r];
}

// ---------------- launch: graph fork/join (copy+q ∥ 4-node chain) ----------
extern "C" void kernel_launch(void* const* d_in, const int* in_sizes, int n_in,
                              void* d_out, int out_size) {
    const float* x         = (const float*)d_in[0];
    const float* q_w       = (const float*)d_in[1];
    const float* in_proj_w = (const float*)d_in[2];
    const float* conv_w    = (const float*)d_in[3];
    const float* conv_b    = (const float*)d_in[4];
    const float* x_proj_w  = (const float*)d_in[5];
    const float* dt_w      = (const float*)d_in[6];
    const float* dt_b      = (const float*)d_in[7];
    // d_in[8] = A_log (unused: h0 = 0 at the single contributing scan step)
    const float* Dv        = (const float*)d_in[9];
    const float* out_proj_w= (const float*)d_in[10];
    const float* proj_w    = (const float*)d_in[11];
    const float* proj_b    = (const float*)d_in[12];
    float* out = (float*)d_out;

    static cudaStream_t s1 = nullptr;
    static cudaEvent_t  e0 = nullptr, e1 = nullptr;
    static bool tried = false;
    if (!tried) {
        tried = true;
        if (cudaStreamCreateWithFlags(&s1, cudaStreamNonBlocking) != cudaSuccess)
            s1 = nullptr;
        if (s1 && (cudaEventCreateWithFlags(&e0, cudaEventDisableTiming) != cudaSuccess ||
                   cudaEventCreateWithFlags(&e1, cudaEventDisableTiming) != cudaSuccess)) {
            s1 = nullptr; e0 = nullptr; e1 = nullptr;
        }
        cudaGetLastError();
    }

    if (s1 && e0 && e1) {
        // fork: chain branch on s1 runs alongside copy+q on the main stream.
        // NOTE: xz depends on g_q, written by the q blocks of k_copy_q. The
        // fork edge alone doesn't order them, so the side stream must wait on
        // an event recorded AFTER k_copy_q.
        k_copy_q<<<Q_BLOCKS + COPY_BLOCKS, 256, 0, 0>>>(x, q_w, in_proj_w, out);
        cudaEventRecord(e0, 0);
        cudaStreamWaitEvent(s1, e0, 0);

        k_xz   <<<1024, 256, 0, s1>>>(in_proj_w, conv_w, conv_b,
                                      x_proj_w, dt_w, out_proj_w);
        k_scan <<<B_SZ, 1024, 0, s1>>>(x_proj_w, dt_w, dt_b, Dv, proj_w);
        k_mixed<<<256,  256, 0, s1>>>(out_proj_w);
        k_out  <<<256,  256, 0, s1>>>(proj_w, proj_b, out);

        // join back into the main stream
        cudaEventRecord(e1, s1);
        cudaStreamWaitEvent(0, e1, 0);
    } else {
        // serial fallback (identical math; R2-class performance)
        k_copy_q<<<Q_BLOCKS + COPY_BLOCKS, 256>>>(x, q_w, in_proj_w, out);
        k_xz   <<<1024, 256>>>(in_proj_w, conv_w, conv_b,
                               x_proj_w, dt_w, out_proj_w);
        k_scan <<<B_SZ, 1024>>>(x_proj_w, dt_w, dt_b, Dv, proj_w);
        k_mixed<<<256,  256>>>(out_proj_w);
        k_out  <<<256,  256>>>(proj_w, proj_b, out);
    }
}